// round 12
// baseline (speedup 1.0000x reference)
#include <cuda_runtime.h>

// Problem constants (fixed by the dataset; runtime values cross-checked from in_sizes)
#define NN 100000
#define EE 1600000

// ---------------- device scratch (static globals: no allocs allowed) ----------------
__device__ float g_deg_out[NN];
__device__ float g_deg_in[NN];
__device__ float g_onorm[NN];
__device__ float g_inorm[NN];
__device__ float g_io[NN];            // onorm * inorm
__device__ float g_p[NN * 40];        // (x*onorm) @ W12
__device__ float g_aggPs[NN * 40];    // io[n] * gather(p)
__device__ float g_W12[256 * 40];     // W1 @ W2
__device__ float g_c2[40];            // b1 @ W2
__device__ int   g_esrc[EE];          // CSR: src ids grouped by dst
__device__ int   g_rowpart[NN];       // per-block exclusive scan partials
__device__ int   g_rowstart[NN];      // CSR row offsets
__device__ int   g_cursor[NN];        // placement cursors
__device__ int   g_bsum[128];

// ---------------- small PTX helpers ----------------
__device__ __forceinline__ unsigned long long pack2(float lo, float hi) {
    unsigned long long r;
    asm("mov.b64 %0, {%1, %2};" : "=l"(r) : "f"(lo), "f"(hi));
    return r;
}
__device__ __forceinline__ void unpack2(unsigned long long v, float& lo, float& hi) {
    asm("mov.b64 {%0, %1}, %2;" : "=f"(lo), "=f"(hi) : "l"(v));
}
// packed dual-FMA: d.lo += a.lo*b.lo ; d.hi += a.hi*b.hi  (FFMA2 on sm_103a)
__device__ __forceinline__ void fma2(unsigned long long& d, unsigned long long a,
                                     unsigned long long b) {
    asm("fma.rn.f32x2 %0, %1, %2, %0;" : "+l"(d) : "l"(a), "l"(b));
}

// Block-wide exclusive scan (all threads must participate). nwarps = blockDim/32.
__device__ __forceinline__ int block_exscan(int v, int* total, int nwarps) {
    __shared__ int wsum[32];
    int tid = threadIdx.x, lane = tid & 31, wid = tid >> 5;
    int inc = v;
#pragma unroll
    for (int o = 1; o < 32; o <<= 1) {
        int t = __shfl_up_sync(0xffffffffu, inc, o);
        if (lane >= o) inc += t;
    }
    if (lane == 31) wsum[wid] = inc;
    __syncthreads();
    if (wid == 0) {
        int s = (lane < nwarps) ? wsum[lane] : 0;
#pragma unroll
        for (int o = 1; o < 32; o <<= 1) {
            int t = __shfl_up_sync(0xffffffffu, s, o);
            if (lane >= o) s += t;
        }
        if (lane < nwarps) wsum[lane] = s;
    }
    __syncthreads();
    int base = (wid > 0) ? wsum[wid - 1] : 0;
    *total = wsum[nwarps - 1];
    return base + inc - v;
}

// ---------------- kernels ----------------

// Zero degree counters only (everything else is overwritten each replay)
__global__ void k_zero() {
    int i = blockIdx.x * blockDim.x + threadIdx.x;
    if (i < NN / 4) {
        float4 z = make_float4(0.f, 0.f, 0.f, 0.f);
        ((float4*)g_deg_out)[i] = z;
        ((float4*)g_deg_in)[i] = z;
    }
}

__global__ void k_degree(const int* __restrict__ src, const int* __restrict__ dst, int e_cnt) {
    int i = blockIdx.x * blockDim.x + threadIdx.x;
    if (i < e_cnt) {
        atomicAdd(&g_deg_out[src[i]], 1.0f);  // result unused -> REDG
        atomicAdd(&g_deg_in[dst[i]], 1.0f);
    }
}

// Fused: [blocks 0..nscan) norms + scan phase A (per-block partial scan of in_deg)
//        [blocks nscan..nscan+10) W12 = W1@W2 and c2 = b1@W2
__global__ __launch_bounds__(1024) void k_fusedA(const float* __restrict__ W1,
                                                 const float* __restrict__ W2,
                                                 const float* __restrict__ b1,
                                                 int n, int nscan) {
    int b = blockIdx.x;
    if (b < nscan) {
        int i = b * 1024 + threadIdx.x;
        float din = (i < n) ? g_deg_in[i] : 0.f;
        if (i < n) {
            float dout = g_deg_out[i];
            float on = rsqrtf(fmaxf(dout, 1.0f));
            float inr = rsqrtf(fmaxf(din, 1.0f));
            g_onorm[i] = on;
            g_inorm[i] = inr;
            g_io[i] = on * inr;
        }
        int total;
        int ex = block_exscan((int)din, &total, 32);
        if (i < n) g_rowpart[i] = ex;
        if (threadIdx.x == 0) g_bsum[b] = total;
    } else {
        __shared__ float Ws[64 * 40];
        int tid = threadIdx.x;
        for (int t = tid; t < 64 * 40; t += 1024) Ws[t] = W2[t];
        __syncthreads();
        int gi = (b - nscan) * 1024 + tid;
        if (gi < 256 * 40) {
            int r = gi / 40;
            int c = gi - r * 40;
            float s = 0.f;
#pragma unroll 16
            for (int k = 0; k < 64; k++) s = fmaf(W1[r * 64 + k], Ws[k * 40 + c], s);
            g_W12[gi] = s;
        }
        if (gi < 40) {
            float s = 0.f;
#pragma unroll 16
            for (int k = 0; k < 64; k++) s = fmaf(b1[k], Ws[k * 40 + gi], s);
            g_c2[gi] = s;
        }
    }
}

// Scan phase B+C fused: each block reduces the block sums below it, then writes
// final row offsets + cursors for its 1024 nodes.
__global__ __launch_bounds__(1024) void k_scanC(int n) {
    __shared__ int red[32];
    __shared__ int s_off;
    int tid = threadIdx.x;
    int lane = tid & 31, wid = tid >> 5;
    int v = (tid < blockIdx.x) ? g_bsum[tid] : 0;  // blockIdx.x <= 97 < 1024
#pragma unroll
    for (int o = 16; o > 0; o >>= 1) v += __shfl_down_sync(0xffffffffu, v, o);
    if (lane == 0) red[wid] = v;
    __syncthreads();
    if (wid == 0) {
        int s = red[lane];
#pragma unroll
        for (int o = 16; o > 0; o >>= 1) s += __shfl_down_sync(0xffffffffu, s, o);
        if (lane == 0) s_off = s;
    }
    __syncthreads();
    int i = blockIdx.x * 1024 + tid;
    if (i < n) {
        int rs = g_rowpart[i] + s_off;
        g_rowstart[i] = rs;
        g_cursor[i] = rs;
    }
}

// CSR placement: group src ids by dst
__global__ void k_place(const int* __restrict__ src, const int* __restrict__ dst, int e_cnt) {
    int i = blockIdx.x * blockDim.x + threadIdx.x;
    if (i < e_cnt) {
        int pos = atomicAdd(&g_cursor[dst[i]], 1);
        g_esrc[pos] = src[i];
    }
}

// GEMM: p[n,40] = (x[n,256] * onorm[n]) @ W12[256,40]
// Block tile 256 rows x 40 cols, BK=16, 256 threads, FFMA2 accumulators.
// Next K-tile is prefetched into registers before the compute phase so global
// latency overlaps the FMA2 loop.
__global__ __launch_bounds__(256) void k_gemmP(const float* __restrict__ x, int n) {
    __shared__ float As[16][258];
    __shared__ unsigned long long Bsd[16][40];
    __shared__ float Ns[256];

    int tid = threadIdx.x;
    int brow = blockIdx.x * 256;
    int tx = tid & 7;    // cols tx*5 .. tx*5+4
    int ty = tid >> 3;   // rows ty*8 .. ty*8+7

    {
        int r = brow + tid;
        Ns[tid] = (r < n) ? g_onorm[r] : 0.f;
    }
    __syncthreads();

    unsigned long long acc[4][5];
#pragma unroll
    for (int i = 0; i < 4; i++)
#pragma unroll
        for (int j = 0; j < 5; j++) acc[i][j] = 0ull;

    float4 av[4];
    float bv[3];

    auto load_tiles = [&](int k0) {
#pragma unroll
        for (int t = 0; t < 4; t++) {
            int idx = tid + t * 256;
            int row = idx >> 2;
            int kk = (idx & 3) << 2;
            int gr = brow + row;
            av[t] = make_float4(0.f, 0.f, 0.f, 0.f);
            if (gr < n) av[t] = *(const float4*)(x + (size_t)gr * 256 + k0 + kk);
        }
#pragma unroll
        for (int t = 0; t < 3; t++) {
            int idx = tid + t * 256;
            if (idx < 640) {
                int kr = idx / 40;
                int c = idx - kr * 40;
                bv[t] = g_W12[(k0 + kr) * 40 + c];
            }
        }
    };
    auto store_tiles = [&]() {
#pragma unroll
        for (int t = 0; t < 4; t++) {
            int idx = tid + t * 256;
            int row = idx >> 2;
            int kk = (idx & 3) << 2;
            float nm = Ns[row];
            As[kk + 0][row] = av[t].x * nm;
            As[kk + 1][row] = av[t].y * nm;
            As[kk + 2][row] = av[t].z * nm;
            As[kk + 3][row] = av[t].w * nm;
        }
#pragma unroll
        for (int t = 0; t < 3; t++) {
            int idx = tid + t * 256;
            if (idx < 640) {
                int kr = idx / 40;
                int c = idx - kr * 40;
                Bsd[kr][c] = pack2(bv[t], bv[t]);
            }
        }
    };

    load_tiles(0);
    for (int k0 = 0; k0 < 256; k0 += 16) {
        store_tiles();
        __syncthreads();
        if (k0 + 16 < 256) load_tiles(k0 + 16);  // overlap with compute below

#pragma unroll
        for (int k = 0; k < 16; k++) {
            unsigned long long b[5];
#pragma unroll
            for (int j = 0; j < 5; j++) b[j] = Bsd[k][tx * 5 + j];
#pragma unroll
            for (int i2 = 0; i2 < 4; i2++) {
                unsigned long long ap =
                    *(const unsigned long long*)&As[k][(ty << 3) + (i2 << 1)];
#pragma unroll
                for (int j = 0; j < 5; j++) fma2(acc[i2][j], ap, b[j]);
            }
        }
        __syncthreads();
    }

#pragma unroll
    for (int i2 = 0; i2 < 4; i2++) {
        int r0 = brow + (ty << 3) + (i2 << 1);
        float lo[5], hi[5];
#pragma unroll
        for (int j = 0; j < 5; j++) unpack2(acc[i2][j], lo[j], hi[j]);
        if (r0 < n) {
#pragma unroll
            for (int j = 0; j < 5; j++) g_p[(size_t)r0 * 40 + tx * 5 + j] = lo[j];
        }
        if (r0 + 1 < n) {
#pragma unroll
            for (int j = 0; j < 5; j++) g_p[(size_t)(r0 + 1) * 40 + tx * 5 + j] = hi[j];
        }
    }
}

// Gather 1 (warp-per-node): aggPs[node] = io[node] * sum_{e: dst=node} p[src_e]
// Lanes 0..19 each own a float2 of the 40-float row -> one coalesced LDG.64
// per edge, uniform trip count within the warp.
__global__ __launch_bounds__(256) void k_gather1(int n) {
    int gw = (blockIdx.x * 256 + threadIdx.x) >> 5;
    int lane = threadIdx.x & 31;
    if (gw >= n) return;
    int start = g_rowstart[gw];
    int deg = (int)g_deg_in[gw];
    const int* ep = g_esrc + start;
    int col = (lane < 20) ? lane * 2 : 38;  // clamp: lanes 20-31 duplicate, discarded
    float2 acc = make_float2(0.f, 0.f);
    int j = 0;
    for (; j + 4 <= deg; j += 4) {
        int s0 = ep[j], s1 = ep[j + 1], s2 = ep[j + 2], s3 = ep[j + 3];
        float2 v0 = *(const float2*)(g_p + s0 * 40 + col);
        float2 v1 = *(const float2*)(g_p + s1 * 40 + col);
        float2 v2 = *(const float2*)(g_p + s2 * 40 + col);
        float2 v3 = *(const float2*)(g_p + s3 * 40 + col);
        acc.x += v0.x; acc.y += v0.y;
        acc.x += v1.x; acc.y += v1.y;
        acc.x += v2.x; acc.y += v2.y;
        acc.x += v3.x; acc.y += v3.y;
    }
    for (; j < deg; j++) {
        int s = ep[j];
        float2 v = *(const float2*)(g_p + s * 40 + col);
        acc.x += v.x; acc.y += v.y;
    }
    if (lane < 20) {
        float io = g_io[gw];
        *(float2*)(g_aggPs + (size_t)gw * 40 + col) =
            make_float2(acc.x * io, acc.y * io);
    }
}

// Gather 2 + epilogue (warp-per-node):
// out[d] = inorm[d] * ( sum aggPs[src] + c2 * sum onorm[src] ) + b2
__global__ __launch_bounds__(256) void k_gather2(const float* __restrict__ b2,
                                                 float* __restrict__ out, int n) {
    int gw = (blockIdx.x * 256 + threadIdx.x) >> 5;
    int lane = threadIdx.x & 31;
    if (gw >= n) return;
    int start = g_rowstart[gw];
    int deg = (int)g_deg_in[gw];
    const int* ep = g_esrc + start;
    int col = (lane < 20) ? lane * 2 : 38;
    float2 acc = make_float2(0.f, 0.f);
    float son = 0.f;  // every lane computes the same value (broadcast loads)
    int j = 0;
    for (; j + 4 <= deg; j += 4) {
        int s0 = ep[j], s1 = ep[j + 1], s2 = ep[j + 2], s3 = ep[j + 3];
        float2 v0 = *(const float2*)(g_aggPs + (size_t)s0 * 40 + col);
        float2 v1 = *(const float2*)(g_aggPs + (size_t)s1 * 40 + col);
        float2 v2 = *(const float2*)(g_aggPs + (size_t)s2 * 40 + col);
        float2 v3 = *(const float2*)(g_aggPs + (size_t)s3 * 40 + col);
        son += g_onorm[s0]; son += g_onorm[s1];
        son += g_onorm[s2]; son += g_onorm[s3];
        acc.x += v0.x; acc.y += v0.y;
        acc.x += v1.x; acc.y += v1.y;
        acc.x += v2.x; acc.y += v2.y;
        acc.x += v3.x; acc.y += v3.y;
    }
    for (; j < deg; j++) {
        int s = ep[j];
        float2 v = *(const float2*)(g_aggPs + (size_t)s * 40 + col);
        acc.x += v.x; acc.y += v.y;
        son += g_onorm[s];
    }
    if (lane < 20) {
        float2 c2 = *(const float2*)(g_c2 + col);
        float2 bb = *(const float2*)(b2 + col);
        float inr = g_inorm[gw];
        *(float2*)(out + (size_t)gw * 40 + col) =
            make_float2(fmaf(inr, fmaf(c2.x, son, acc.x), bb.x),
                        fmaf(inr, fmaf(c2.y, son, acc.y), bb.y));
    }
}

// ---------------- launch ----------------
extern "C" void kernel_launch(void* const* d_in, const int* in_sizes, int n_in,
                              void* d_out, int out_size) {
    const float* x  = (const float*)d_in[0];
    const int* src  = (const int*)d_in[1];
    const int* dst  = (const int*)d_in[2];
    const float* W1 = (const float*)d_in[3];
    const float* b1 = (const float*)d_in[4];
    const float* W2 = (const float*)d_in[5];
    const float* b2 = (const float*)d_in[6];
    float* out = (float*)d_out;

    int n = in_sizes[0] / 256;   // 100000
    int e = in_sizes[1];         // 1600000

    int nscan = (n + 1023) / 1024;         // 98
    int nprep = (256 * 40 + 1023) / 1024;  // 10
    int ngather = (n * 32 + 255) / 256;    // warp per node, 8 warps/block

    k_zero<<<(NN / 4 + 255) / 256, 256>>>();
    k_degree<<<(e + 255) / 256, 256>>>(src, dst, e);
    k_fusedA<<<nscan + nprep, 1024>>>(W1, W2, b1, n, nscan);
    k_scanC<<<nscan, 1024>>>(n);
    k_place<<<(e + 255) / 256, 256>>>(src, dst, e);
    k_gemmP<<<(n + 255) / 256, 256>>>(x, n);
    k_gather1<<<ngather, 256>>>(n);
    k_gather2<<<ngather, 256>>>(b2, out, n);
}

// round 13
// speedup vs baseline: 1.1706x; 1.1706x over previous
#include <cuda_runtime.h>

// Problem constants (fixed by the dataset; runtime values cross-checked from in_sizes)
#define NN 100000
#define EE 1600000

// ---------------- device scratch (static globals: no allocs allowed) ----------------
__device__ float g_deg_out[NN];
__device__ float g_deg_in[NN];
__device__ float g_onorm[NN];
__device__ float g_inorm[NN];
__device__ float g_io[NN];            // onorm * inorm
__device__ float g_q[NN * 40];        // x @ W12  (UNSCALED; onorm applied in gather1)
__device__ float g_aggPs[NN * 40];    // io[n] * sum_{e:dst=n} onorm[src]*q[src]
__device__ float g_W12[256 * 40];     // W1 @ W2
__device__ float g_c2[40];            // b1 @ W2
__device__ int   g_esrc[EE];          // CSR: src ids grouped by dst
__device__ int   g_rowpart[NN];       // per-block exclusive scan partials
__device__ int   g_rowstart[NN];      // CSR row offsets
__device__ int   g_cursor[NN];        // placement cursors
__device__ int   g_bsum[128];

// ---------------- small PTX helpers ----------------
__device__ __forceinline__ unsigned long long pack2(float lo, float hi) {
    unsigned long long r;
    asm("mov.b64 %0, {%1, %2};" : "=l"(r) : "f"(lo), "f"(hi));
    return r;
}
__device__ __forceinline__ void unpack2(unsigned long long v, float& lo, float& hi) {
    asm("mov.b64 {%0, %1}, %2;" : "=f"(lo), "=f"(hi) : "l"(v));
}
// packed dual-FMA: d.lo += a.lo*b.lo ; d.hi += a.hi*b.hi  (FFMA2 on sm_103a)
__device__ __forceinline__ void fma2(unsigned long long& d, unsigned long long a,
                                     unsigned long long b) {
    asm("fma.rn.f32x2 %0, %1, %2, %0;" : "+l"(d) : "l"(a), "l"(b));
}

// Block-wide exclusive scan (all threads must participate). nwarps = blockDim/32.
__device__ __forceinline__ int block_exscan(int v, int* total, int nwarps) {
    __shared__ int wsum[32];
    int tid = threadIdx.x, lane = tid & 31, wid = tid >> 5;
    int inc = v;
#pragma unroll
    for (int o = 1; o < 32; o <<= 1) {
        int t = __shfl_up_sync(0xffffffffu, inc, o);
        if (lane >= o) inc += t;
    }
    if (lane == 31) wsum[wid] = inc;
    __syncthreads();
    if (wid == 0) {
        int s = (lane < nwarps) ? wsum[lane] : 0;
#pragma unroll
        for (int o = 1; o < 32; o <<= 1) {
            int t = __shfl_up_sync(0xffffffffu, s, o);
            if (lane >= o) s += t;
        }
        if (lane < nwarps) wsum[lane] = s;
    }
    __syncthreads();
    int base = (wid > 0) ? wsum[wid - 1] : 0;
    *total = wsum[nwarps - 1];
    return base + inc - v;
}

// ---------------- kernels ----------------

// Zero degree counters only (everything else is overwritten each replay)
__global__ void k_zero() {
    int i = blockIdx.x * blockDim.x + threadIdx.x;
    if (i < NN / 4) {
        float4 z = make_float4(0.f, 0.f, 0.f, 0.f);
        ((float4*)g_deg_out)[i] = z;
        ((float4*)g_deg_in)[i] = z;
    }
}

__global__ void k_degree(const int* __restrict__ src, const int* __restrict__ dst, int e_cnt) {
    int i = blockIdx.x * blockDim.x + threadIdx.x;
    if (i < e_cnt) {
        atomicAdd(&g_deg_out[src[i]], 1.0f);  // result unused -> REDG
        atomicAdd(&g_deg_in[dst[i]], 1.0f);
    }
}

// norms + scan phase A (per-block partial scan of in_deg)
__global__ __launch_bounds__(1024) void k_norms_scanA(int n) {
    int i = blockIdx.x * 1024 + threadIdx.x;
    float din = (i < n) ? g_deg_in[i] : 0.f;
    if (i < n) {
        float dout = g_deg_out[i];
        float on = rsqrtf(fmaxf(dout, 1.0f));
        float inr = rsqrtf(fmaxf(din, 1.0f));
        g_onorm[i] = on;
        g_inorm[i] = inr;
        g_io[i] = on * inr;
    }
    int total;
    int ex = block_exscan((int)din, &total, 32);
    if (i < n) g_rowpart[i] = ex;
    if (threadIdx.x == 0) g_bsum[blockIdx.x] = total;
}

// Scan phase B+C fused: each block reduces the block sums below it, then writes
// final row offsets + cursors for its 1024 nodes.
__global__ __launch_bounds__(1024) void k_scanC(int n) {
    __shared__ int red[32];
    __shared__ int s_off;
    int tid = threadIdx.x;
    int lane = tid & 31, wid = tid >> 5;
    int v = (tid < blockIdx.x) ? g_bsum[tid] : 0;  // blockIdx.x <= 97 < 1024
#pragma unroll
    for (int o = 16; o > 0; o >>= 1) v += __shfl_down_sync(0xffffffffu, v, o);
    if (lane == 0) red[wid] = v;
    __syncthreads();
    if (wid == 0) {
        int s = red[lane];
#pragma unroll
        for (int o = 16; o > 0; o >>= 1) s += __shfl_down_sync(0xffffffffu, s, o);
        if (lane == 0) s_off = s;
    }
    __syncthreads();
    int i = blockIdx.x * 1024 + tid;
    if (i < n) {
        int rs = g_rowpart[i] + s_off;
        g_rowstart[i] = rs;
        g_cursor[i] = rs;
    }
}

// CSR placement: group src ids by dst
__global__ void k_place(const int* __restrict__ src, const int* __restrict__ dst, int e_cnt) {
    int i = blockIdx.x * blockDim.x + threadIdx.x;
    if (i < e_cnt) {
        int pos = atomicAdd(&g_cursor[dst[i]], 1);
        g_esrc[pos] = src[i];
    }
}

// Precompute W12 = W1 @ W2 (256x40) and c2 = b1 @ W2 (40). W2 cached in smem.
// Runs on the side stream (no dependence on graph data).
__global__ __launch_bounds__(256) void k_prep(const float* __restrict__ W1,
                                              const float* __restrict__ W2,
                                              const float* __restrict__ b1) {
    __shared__ float Ws[64 * 40];
    int tid = threadIdx.x;
    for (int i = tid; i < 64 * 40; i += 256) Ws[i] = W2[i];
    __syncthreads();
    int gi = blockIdx.x * 256 + tid;
    if (gi < 256 * 40) {
        int r = gi / 40;
        int c = gi - r * 40;
        float s = 0.f;
#pragma unroll 16
        for (int k = 0; k < 64; k++) s = fmaf(W1[r * 64 + k], Ws[k * 40 + c], s);
        g_W12[gi] = s;
    }
    if (gi < 40) {
        float s = 0.f;
#pragma unroll 16
        for (int k = 0; k < 64; k++) s = fmaf(b1[k], Ws[k * 40 + gi], s);
        g_c2[gi] = s;
    }
}

// GEMM: q[n,40] = x[n,256] @ W12[256,40]   (no norm scaling -> input-only dep)
// Block tile 256 rows x 40 cols, BK=16, 256 threads, FFMA2 accumulators.
// B stored as scalar floats (dup to f32x2 at use) -> 52B LDS per thread-k.
__global__ __launch_bounds__(256) void k_gemmQ(const float* __restrict__ x, int n) {
    __shared__ float As[16][258];  // [k][row], stride 258 -> conflict-free
    __shared__ float Bs[16][40];

    int tid = threadIdx.x;
    int brow = blockIdx.x * 256;
    int tx = tid & 7;    // cols tx*5 .. tx*5+4
    int ty = tid >> 3;   // rows ty*8 .. ty*8+7

    unsigned long long acc[4][5];
#pragma unroll
    for (int i = 0; i < 4; i++)
#pragma unroll
        for (int j = 0; j < 5; j++) acc[i][j] = 0ull;

    for (int k0 = 0; k0 < 256; k0 += 16) {
        // A tile: 256 rows x 16 k, transposed (4 float4 loads/thread)
#pragma unroll
        for (int t = 0; t < 4; t++) {
            int idx = tid + t * 256;     // 0..1023
            int row = idx >> 2;          // 0..255
            int kk = (idx & 3) << 2;     // 0,4,8,12
            int gr = brow + row;
            float4 v = make_float4(0.f, 0.f, 0.f, 0.f);
            if (gr < n) v = *(const float4*)(x + (size_t)gr * 256 + k0 + kk);
            As[kk + 0][row] = v.x;
            As[kk + 1][row] = v.y;
            As[kk + 2][row] = v.z;
            As[kk + 3][row] = v.w;
        }
        // B tile 16x40 (scalar)
#pragma unroll
        for (int t = 0; t < 3; t++) {
            int idx = tid + t * 256;
            if (idx < 640) {
                int kr = idx / 40;
                int c = idx - kr * 40;
                Bs[kr][c] = g_W12[(k0 + kr) * 40 + c];
            }
        }
        __syncthreads();

#pragma unroll
        for (int k = 0; k < 16; k++) {
            unsigned long long b[5];
#pragma unroll
            for (int j = 0; j < 5; j++) {
                float w = Bs[k][tx * 5 + j];
                b[j] = pack2(w, w);
            }
#pragma unroll
            for (int i2 = 0; i2 < 4; i2++) {
                unsigned long long ap =
                    *(const unsigned long long*)&As[k][(ty << 3) + (i2 << 1)];
#pragma unroll
                for (int j = 0; j < 5; j++) fma2(acc[i2][j], ap, b[j]);
            }
        }
        __syncthreads();
    }

    // store q
#pragma unroll
    for (int i2 = 0; i2 < 4; i2++) {
        int r0 = brow + (ty << 3) + (i2 << 1);
        float lo[5], hi[5];
#pragma unroll
        for (int j = 0; j < 5; j++) unpack2(acc[i2][j], lo[j], hi[j]);
        if (r0 < n) {
#pragma unroll
            for (int j = 0; j < 5; j++) g_q[(size_t)r0 * 40 + tx * 5 + j] = lo[j];
        }
        if (r0 + 1 < n) {
#pragma unroll
            for (int j = 0; j < 5; j++) g_q[(size_t)(r0 + 1) * 40 + tx * 5 + j] = hi[j];
        }
    }
}

// Gather 1 (thread = (node, float4-chunk), proven R10 layout):
// aggPs[node] = io[node] * sum_{e: dst=node} onorm[src_e] * q[src_e]
__global__ void k_gather1(int n) {
    int i = blockIdx.x * blockDim.x + threadIdx.x;
    if (i >= n * 10) return;
    int node = i / 10;
    int c = (i - node * 10) << 2;
    int start = g_rowstart[node];
    int deg = (int)g_deg_in[node];
    const int* ep = g_esrc + start;
    float4 acc = make_float4(0.f, 0.f, 0.f, 0.f);
    int j = 0;
    for (; j + 4 <= deg; j += 4) {
        int s0 = ep[j], s1 = ep[j + 1], s2 = ep[j + 2], s3 = ep[j + 3];
        float o0 = g_onorm[s0], o1 = g_onorm[s1], o2 = g_onorm[s2], o3 = g_onorm[s3];
        float4 v0 = *(const float4*)(g_q + s0 * 40 + c);
        float4 v1 = *(const float4*)(g_q + s1 * 40 + c);
        float4 v2 = *(const float4*)(g_q + s2 * 40 + c);
        float4 v3 = *(const float4*)(g_q + s3 * 40 + c);
        acc.x = fmaf(o0, v0.x, acc.x); acc.y = fmaf(o0, v0.y, acc.y);
        acc.z = fmaf(o0, v0.z, acc.z); acc.w = fmaf(o0, v0.w, acc.w);
        acc.x = fmaf(o1, v1.x, acc.x); acc.y = fmaf(o1, v1.y, acc.y);
        acc.z = fmaf(o1, v1.z, acc.z); acc.w = fmaf(o1, v1.w, acc.w);
        acc.x = fmaf(o2, v2.x, acc.x); acc.y = fmaf(o2, v2.y, acc.y);
        acc.z = fmaf(o2, v2.z, acc.z); acc.w = fmaf(o2, v2.w, acc.w);
        acc.x = fmaf(o3, v3.x, acc.x); acc.y = fmaf(o3, v3.y, acc.y);
        acc.z = fmaf(o3, v3.z, acc.z); acc.w = fmaf(o3, v3.w, acc.w);
    }
    for (; j < deg; j++) {
        int s = ep[j];
        float o = g_onorm[s];
        float4 v = *(const float4*)(g_q + s * 40 + c);
        acc.x = fmaf(o, v.x, acc.x); acc.y = fmaf(o, v.y, acc.y);
        acc.z = fmaf(o, v.z, acc.z); acc.w = fmaf(o, v.w, acc.w);
    }
    float io = g_io[node];
    *(float4*)(g_aggPs + (size_t)node * 40 + c) =
        make_float4(acc.x * io, acc.y * io, acc.z * io, acc.w * io);
}

// Gather 2 + epilogue (proven R10 layout):
// out[d] = inorm[d] * ( sum aggPs[src] + c2 * sum onorm[src] ) + b2
__global__ void k_gather2(const float* __restrict__ b2, float* __restrict__ out, int n) {
    int i = blockIdx.x * blockDim.x + threadIdx.x;
    if (i >= n * 10) return;
    int node = i / 10;
    int c = (i - node * 10) << 2;
    int start = g_rowstart[node];
    int deg = (int)g_deg_in[node];
    const int* ep = g_esrc + start;
    float4 acc = make_float4(0.f, 0.f, 0.f, 0.f);
    float son = 0.f;
    int j = 0;
    for (; j + 2 <= deg; j += 2) {
        int s0 = ep[j], s1 = ep[j + 1];
        float4 v0 = *(const float4*)(g_aggPs + (size_t)s0 * 40 + c);
        float4 v1 = *(const float4*)(g_aggPs + (size_t)s1 * 40 + c);
        float o0 = g_onorm[s0], o1 = g_onorm[s1];
        acc.x += v0.x; acc.y += v0.y; acc.z += v0.z; acc.w += v0.w;
        acc.x += v1.x; acc.y += v1.y; acc.z += v1.z; acc.w += v1.w;
        son += o0; son += o1;
    }
    for (; j < deg; j++) {
        int s = ep[j];
        float4 v = *(const float4*)(g_aggPs + (size_t)s * 40 + c);
        acc.x += v.x; acc.y += v.y; acc.z += v.z; acc.w += v.w;
        son += g_onorm[s];
    }
    float4 c2 = *(const float4*)(g_c2 + c);
    float4 bb = *(const float4*)(b2 + c);
    float inr = g_inorm[node];
    *(float4*)(out + (size_t)node * 40 + c) =
        make_float4(fmaf(inr, fmaf(c2.x, son, acc.x), bb.x),
                    fmaf(inr, fmaf(c2.y, son, acc.y), bb.y),
                    fmaf(inr, fmaf(c2.z, son, acc.z), bb.z),
                    fmaf(inr, fmaf(c2.w, son, acc.w), bb.w));
}

// ---------------- launch ----------------
// Two independent chains run concurrently (graph DAG fork/join):
//   default stream: zero -> degree -> norms/scan -> scanC -> place   (atomic/L2 bound)
//   side stream:    prep(W12) -> gemmQ                               (FMA/LDS bound)
// join before gather1 (needs CSR + q + norms).
extern "C" void kernel_launch(void* const* d_in, const int* in_sizes, int n_in,
                              void* d_out, int out_size) {
    const float* x  = (const float*)d_in[0];
    const int* src  = (const int*)d_in[1];
    const int* dst  = (const int*)d_in[2];
    const float* W1 = (const float*)d_in[3];
    const float* b1 = (const float*)d_in[4];
    const float* W2 = (const float*)d_in[5];
    const float* b2 = (const float*)d_in[6];
    float* out = (float*)d_out;

    int n = in_sizes[0] / 256;   // 100000
    int e = in_sizes[1];         // 1600000

    int nscan = (n + 1023) / 1024;  // 98

    static bool s_init = false;
    static cudaStream_t s1;
    static cudaEvent_t evFork, evJoin;
    if (!s_init) {  // one-time infra setup (first call is outside graph capture)
        cudaStreamCreateWithFlags(&s1, cudaStreamNonBlocking);
        cudaEventCreateWithFlags(&evFork, cudaEventDisableTiming);
        cudaEventCreateWithFlags(&evJoin, cudaEventDisableTiming);
        s_init = true;
    }

    // fork side stream off the (captured) default stream
    cudaEventRecord(evFork, 0);
    cudaStreamWaitEvent(s1, evFork, 0);
    k_prep<<<40, 256, 0, s1>>>(W1, W2, b1);
    k_gemmQ<<<(n + 255) / 256, 256, 0, s1>>>(x, n);
    cudaEventRecord(evJoin, s1);

    // main chain on the default stream
    k_zero<<<(NN / 4 + 255) / 256, 256>>>();
    k_degree<<<(e + 255) / 256, 256>>>(src, dst, e);
    k_norms_scanA<<<nscan, 1024>>>(n);
    k_scanC<<<nscan, 1024>>>(n);
    k_place<<<(e + 255) / 256, 256>>>(src, dst, e);

    // join: gathers need both chains
    cudaStreamWaitEvent(0, evJoin, 0);
    k_gather1<<<(n * 10 + 255) / 256, 256>>>(n);
    k_gather2<<<(n * 10 + 255) / 256, 256>>>(b2, out, n);
}

// round 14
// speedup vs baseline: 1.1910x; 1.0175x over previous
#include <cuda_runtime.h>

// Problem constants (fixed by the dataset; runtime values cross-checked from in_sizes)
#define NN 100000
#define EE 1600000

// ---------------- device scratch (static globals: no allocs allowed) ----------------
__device__ float g_deg_out[NN];
__device__ float g_deg_in[NN];
__device__ float g_onorm[NN];
__device__ float g_inorm[NN];
__device__ float g_io[NN];            // onorm * inorm
__device__ float g_q[NN * 40];        // x @ W12, then scaled in-place by onorm (=p)
__device__ float g_aggPs[NN * 40];    // io[n] * sum_{e:dst=n} p[src]
__device__ float g_son[NN];           // sum_{e:dst=n} onorm[src]
__device__ float g_W12[256 * 40];     // W1 @ W2
__device__ float g_c2[40];            // b1 @ W2
__device__ int   g_esrc[EE];          // CSR: src ids grouped by dst
__device__ int   g_rowpart[NN];       // per-block exclusive scan partials
__device__ int   g_rowstart[NN];      // CSR row offsets
__device__ int   g_cursor[NN];        // placement cursors
__device__ int   g_bsum[128];

// ---------------- small PTX helpers ----------------
__device__ __forceinline__ unsigned long long pack2(float lo, float hi) {
    unsigned long long r;
    asm("mov.b64 %0, {%1, %2};" : "=l"(r) : "f"(lo), "f"(hi));
    return r;
}
__device__ __forceinline__ void unpack2(unsigned long long v, float& lo, float& hi) {
    asm("mov.b64 {%0, %1}, %2;" : "=f"(lo), "=f"(hi) : "l"(v));
}
// packed dual-FMA: d.lo += a.lo*b.lo ; d.hi += a.hi*b.hi  (FFMA2 on sm_103a)
__device__ __forceinline__ void fma2(unsigned long long& d, unsigned long long a,
                                     unsigned long long b) {
    asm("fma.rn.f32x2 %0, %1, %2, %0;" : "+l"(d) : "l"(a), "l"(b));
}

// Block-wide exclusive scan (all threads must participate). nwarps = blockDim/32.
__device__ __forceinline__ int block_exscan(int v, int* total, int nwarps) {
    __shared__ int wsum[32];
    int tid = threadIdx.x, lane = tid & 31, wid = tid >> 5;
    int inc = v;
#pragma unroll
    for (int o = 1; o < 32; o <<= 1) {
        int t = __shfl_up_sync(0xffffffffu, inc, o);
        if (lane >= o) inc += t;
    }
    if (lane == 31) wsum[wid] = inc;
    __syncthreads();
    if (wid == 0) {
        int s = (lane < nwarps) ? wsum[lane] : 0;
#pragma unroll
        for (int o = 1; o < 32; o <<= 1) {
            int t = __shfl_up_sync(0xffffffffu, s, o);
            if (lane >= o) s += t;
        }
        if (lane < nwarps) wsum[lane] = s;
    }
    __syncthreads();
    int base = (wid > 0) ? wsum[wid - 1] : 0;
    *total = wsum[nwarps - 1];
    return base + inc - v;
}

// ---------------- kernels ----------------

// Zero degree counters only (everything else is overwritten each replay)
__global__ void k_zero() {
    int i = blockIdx.x * blockDim.x + threadIdx.x;
    if (i < NN / 4) {
        float4 z = make_float4(0.f, 0.f, 0.f, 0.f);
        ((float4*)g_deg_out)[i] = z;
        ((float4*)g_deg_in)[i] = z;
    }
}

__global__ void k_degree(const int* __restrict__ src, const int* __restrict__ dst, int e_cnt) {
    int i = blockIdx.x * blockDim.x + threadIdx.x;
    if (i < e_cnt) {
        atomicAdd(&g_deg_out[src[i]], 1.0f);  // result unused -> REDG
        atomicAdd(&g_deg_in[dst[i]], 1.0f);
    }
}

// norms + scan phase A (per-block partial scan of in_deg)
__global__ __launch_bounds__(1024) void k_norms_scanA(int n) {
    int i = blockIdx.x * 1024 + threadIdx.x;
    float din = (i < n) ? g_deg_in[i] : 0.f;
    if (i < n) {
        float dout = g_deg_out[i];
        float on = rsqrtf(fmaxf(dout, 1.0f));
        float inr = rsqrtf(fmaxf(din, 1.0f));
        g_onorm[i] = on;
        g_inorm[i] = inr;
        g_io[i] = on * inr;
    }
    int total;
    int ex = block_exscan((int)din, &total, 32);
    if (i < n) g_rowpart[i] = ex;
    if (threadIdx.x == 0) g_bsum[blockIdx.x] = total;
}

// Scan phase B+C fused: each block reduces the block sums below it, then writes
// final row offsets + cursors for its 1024 nodes.
__global__ __launch_bounds__(1024) void k_scanC(int n) {
    __shared__ int red[32];
    __shared__ int s_off;
    int tid = threadIdx.x;
    int lane = tid & 31, wid = tid >> 5;
    int v = (tid < blockIdx.x) ? g_bsum[tid] : 0;  // blockIdx.x <= 97 < 1024
#pragma unroll
    for (int o = 16; o > 0; o >>= 1) v += __shfl_down_sync(0xffffffffu, v, o);
    if (lane == 0) red[wid] = v;
    __syncthreads();
    if (wid == 0) {
        int s = red[lane];
#pragma unroll
        for (int o = 16; o > 0; o >>= 1) s += __shfl_down_sync(0xffffffffu, s, o);
        if (lane == 0) s_off = s;
    }
    __syncthreads();
    int i = blockIdx.x * 1024 + tid;
    if (i < n) {
        int rs = g_rowpart[i] + s_off;
        g_rowstart[i] = rs;
        g_cursor[i] = rs;
    }
}

// CSR placement: group src ids by dst
__global__ void k_place(const int* __restrict__ src, const int* __restrict__ dst, int e_cnt) {
    int i = blockIdx.x * blockDim.x + threadIdx.x;
    if (i < e_cnt) {
        int pos = atomicAdd(&g_cursor[dst[i]], 1);
        g_esrc[pos] = src[i];
    }
}

// Precompute W12 = W1 @ W2 (256x40) and c2 = b1 @ W2 (40). W2 cached in smem.
// Runs on the side stream (no dependence on graph data).
__global__ __launch_bounds__(256) void k_prep(const float* __restrict__ W1,
                                              const float* __restrict__ W2,
                                              const float* __restrict__ b1) {
    __shared__ float Ws[64 * 40];
    int tid = threadIdx.x;
    for (int i = tid; i < 64 * 40; i += 256) Ws[i] = W2[i];
    __syncthreads();
    int gi = blockIdx.x * 256 + tid;
    if (gi < 256 * 40) {
        int r = gi / 40;
        int c = gi - r * 40;
        float s = 0.f;
#pragma unroll 16
        for (int k = 0; k < 64; k++) s = fmaf(W1[r * 64 + k], Ws[k * 40 + c], s);
        g_W12[gi] = s;
    }
    if (gi < 40) {
        float s = 0.f;
#pragma unroll 16
        for (int k = 0; k < 64; k++) s = fmaf(b1[k], Ws[k * 40 + gi], s);
        g_c2[gi] = s;
    }
}

// GEMM: q[n,40] = x[n,256] @ W12[256,40]   (no norm scaling -> input-only dep)
// Block tile 256 rows x 40 cols, BK=16, 256 threads, FFMA2 accumulators.
__global__ __launch_bounds__(256) void k_gemmQ(const float* __restrict__ x, int n) {
    __shared__ float As[16][258];  // [k][row], stride 258 -> conflict-free
    __shared__ float Bs[16][40];

    int tid = threadIdx.x;
    int brow = blockIdx.x * 256;
    int tx = tid & 7;    // cols tx*5 .. tx*5+4
    int ty = tid >> 3;   // rows ty*8 .. ty*8+7

    unsigned long long acc[4][5];
#pragma unroll
    for (int i = 0; i < 4; i++)
#pragma unroll
        for (int j = 0; j < 5; j++) acc[i][j] = 0ull;

    for (int k0 = 0; k0 < 256; k0 += 16) {
        // A tile: 256 rows x 16 k, transposed (4 float4 loads/thread)
#pragma unroll
        for (int t = 0; t < 4; t++) {
            int idx = tid + t * 256;     // 0..1023
            int row = idx >> 2;          // 0..255
            int kk = (idx & 3) << 2;     // 0,4,8,12
            int gr = brow + row;
            float4 v = make_float4(0.f, 0.f, 0.f, 0.f);
            if (gr < n) v = *(const float4*)(x + (size_t)gr * 256 + k0 + kk);
            As[kk + 0][row] = v.x;
            As[kk + 1][row] = v.y;
            As[kk + 2][row] = v.z;
            As[kk + 3][row] = v.w;
        }
        // B tile 16x40 (scalar)
#pragma unroll
        for (int t = 0; t < 3; t++) {
            int idx = tid + t * 256;
            if (idx < 640) {
                int kr = idx / 40;
                int c = idx - kr * 40;
                Bs[kr][c] = g_W12[(k0 + kr) * 40 + c];
            }
        }
        __syncthreads();

#pragma unroll
        for (int k = 0; k < 16; k++) {
            unsigned long long b[5];
#pragma unroll
            for (int j = 0; j < 5; j++) {
                float w = Bs[k][tx * 5 + j];
                b[j] = pack2(w, w);
            }
#pragma unroll
            for (int i2 = 0; i2 < 4; i2++) {
                unsigned long long ap =
                    *(const unsigned long long*)&As[k][(ty << 3) + (i2 << 1)];
#pragma unroll
                for (int j = 0; j < 5; j++) fma2(acc[i2][j], ap, b[j]);
            }
        }
        __syncthreads();
    }

    // store q
#pragma unroll
    for (int i2 = 0; i2 < 4; i2++) {
        int r0 = brow + (ty << 3) + (i2 << 1);
        float lo[5], hi[5];
#pragma unroll
        for (int j = 0; j < 5; j++) unpack2(acc[i2][j], lo[j], hi[j]);
        if (r0 < n) {
#pragma unroll
            for (int j = 0; j < 5; j++) g_q[(size_t)r0 * 40 + tx * 5 + j] = lo[j];
        }
        if (r0 + 1 < n) {
#pragma unroll
            for (int j = 0; j < 5; j++) g_q[(size_t)(r0 + 1) * 40 + tx * 5 + j] = hi[j];
        }
    }
}

// In-place scale: q[row,:] *= onorm[row]  (runs on side stream after evNorms,
// overlapped with k_place on the main stream)
__global__ void k_scaleP(int n) {
    int i = blockIdx.x * blockDim.x + threadIdx.x;  // float4 index
    if (i >= n * 10) return;
    int row = i / 10;
    float o = g_onorm[row];
    float4 v = ((const float4*)g_q)[i];
    ((float4*)g_q)[i] = make_float4(v.x * o, v.y * o, v.z * o, v.w * o);
}

// Gather 1 (thread = (node, float4-chunk), proven R10 layout):
// aggPs[node] = io[node] * sum_{e: dst=node} p[src_e]      (p = scaled q)
// chunk-0 lane additionally accumulates son[node] = sum onorm[src_e]
__global__ void k_gather1(int n) {
    int i = blockIdx.x * blockDim.x + threadIdx.x;
    if (i >= n * 10) return;
    int node = i / 10;
    int ch = i - node * 10;
    int c = ch << 2;
    int start = g_rowstart[node];
    int deg = (int)g_deg_in[node];
    const int* ep = g_esrc + start;
    bool lead = (ch == 0);
    float4 acc = make_float4(0.f, 0.f, 0.f, 0.f);
    float son = 0.f;
    int j = 0;
    for (; j + 4 <= deg; j += 4) {
        int s0 = ep[j], s1 = ep[j + 1], s2 = ep[j + 2], s3 = ep[j + 3];
        float4 v0 = *(const float4*)(g_q + s0 * 40 + c);
        float4 v1 = *(const float4*)(g_q + s1 * 40 + c);
        float4 v2 = *(const float4*)(g_q + s2 * 40 + c);
        float4 v3 = *(const float4*)(g_q + s3 * 40 + c);
        if (lead) { son += g_onorm[s0] + g_onorm[s1] + g_onorm[s2] + g_onorm[s3]; }
        acc.x += v0.x; acc.y += v0.y; acc.z += v0.z; acc.w += v0.w;
        acc.x += v1.x; acc.y += v1.y; acc.z += v1.z; acc.w += v1.w;
        acc.x += v2.x; acc.y += v2.y; acc.z += v2.z; acc.w += v2.w;
        acc.x += v3.x; acc.y += v3.y; acc.z += v3.z; acc.w += v3.w;
    }
    for (; j < deg; j++) {
        int s = ep[j];
        float4 v = *(const float4*)(g_q + s * 40 + c);
        if (lead) son += g_onorm[s];
        acc.x += v.x; acc.y += v.y; acc.z += v.z; acc.w += v.w;
    }
    float io = g_io[node];
    *(float4*)(g_aggPs + (size_t)node * 40 + c) =
        make_float4(acc.x * io, acc.y * io, acc.z * io, acc.w * io);
    if (lead) g_son[node] = son;
}

// Gather 2 + epilogue:
// out[d] = inorm[d] * ( sum aggPs[src] + c2 * son[d] ) + b2
__global__ void k_gather2(const float* __restrict__ b2, float* __restrict__ out, int n) {
    int i = blockIdx.x * blockDim.x + threadIdx.x;
    if (i >= n * 10) return;
    int node = i / 10;
    int c = (i - node * 10) << 2;
    int start = g_rowstart[node];
    int deg = (int)g_deg_in[node];
    const int* ep = g_esrc + start;
    float4 acc = make_float4(0.f, 0.f, 0.f, 0.f);
    int j = 0;
    for (; j + 4 <= deg; j += 4) {
        int s0 = ep[j], s1 = ep[j + 1], s2 = ep[j + 2], s3 = ep[j + 3];
        float4 v0 = *(const float4*)(g_aggPs + (size_t)s0 * 40 + c);
        float4 v1 = *(const float4*)(g_aggPs + (size_t)s1 * 40 + c);
        float4 v2 = *(const float4*)(g_aggPs + (size_t)s2 * 40 + c);
        float4 v3 = *(const float4*)(g_aggPs + (size_t)s3 * 40 + c);
        acc.x += v0.x; acc.y += v0.y; acc.z += v0.z; acc.w += v0.w;
        acc.x += v1.x; acc.y += v1.y; acc.z += v1.z; acc.w += v1.w;
        acc.x += v2.x; acc.y += v2.y; acc.z += v2.z; acc.w += v2.w;
        acc.x += v3.x; acc.y += v3.y; acc.z += v3.z; acc.w += v3.w;
    }
    for (; j < deg; j++) {
        int s = ep[j];
        float4 v = *(const float4*)(g_aggPs + (size_t)s * 40 + c);
        acc.x += v.x; acc.y += v.y; acc.z += v.z; acc.w += v.w;
    }
    float son = g_son[node];
    float4 c2 = *(const float4*)(g_c2 + c);
    float4 bb = *(const float4*)(b2 + c);
    float inr = g_inorm[node];
    *(float4*)(out + (size_t)node * 40 + c) =
        make_float4(fmaf(inr, fmaf(c2.x, son, acc.x), bb.x),
                    fmaf(inr, fmaf(c2.y, son, acc.y), bb.y),
                    fmaf(inr, fmaf(c2.z, son, acc.z), bb.z),
                    fmaf(inr, fmaf(c2.w, son, acc.w), bb.w));
}

// ---------------- launch ----------------
// DAG (graph capture encodes the fork/join):
//   main:  zero -> degree -> norms/scanA -> scanC -> place -> [join] -> gather1 -> gather2
//   side:  prep -> gemmQ -> [wait norms] -> scaleP -> [join]
extern "C" void kernel_launch(void* const* d_in, const int* in_sizes, int n_in,
                              void* d_out, int out_size) {
    const float* x  = (const float*)d_in[0];
    const int* src  = (const int*)d_in[1];
    const int* dst  = (const int*)d_in[2];
    const float* W1 = (const float*)d_in[3];
    const float* b1 = (const float*)d_in[4];
    const float* W2 = (const float*)d_in[5];
    const float* b2 = (const float*)d_in[6];
    float* out = (float*)d_out;

    int n = in_sizes[0] / 256;   // 100000
    int e = in_sizes[1];         // 1600000

    int nscan = (n + 1023) / 1024;  // 98

    static bool s_init = false;
    static cudaStream_t s1;
    static cudaEvent_t evFork, evNorms, evJoin;
    if (!s_init) {  // one-time infra setup (first call is outside graph capture)
        cudaStreamCreateWithFlags(&s1, cudaStreamNonBlocking);
        cudaEventCreateWithFlags(&evFork, cudaEventDisableTiming);
        cudaEventCreateWithFlags(&evNorms, cudaEventDisableTiming);
        cudaEventCreateWithFlags(&evJoin, cudaEventDisableTiming);
        s_init = true;
    }

    // fork side stream off the (captured) default stream
    cudaEventRecord(evFork, 0);
    cudaStreamWaitEvent(s1, evFork, 0);
    k_prep<<<40, 256, 0, s1>>>(W1, W2, b1);
    k_gemmQ<<<(n + 255) / 256, 256, 0, s1>>>(x, n);

    // main chain on the default stream
    k_zero<<<(NN / 4 + 255) / 256, 256>>>();
    k_degree<<<(e + 255) / 256, 256>>>(src, dst, e);
    k_norms_scanA<<<nscan, 1024>>>(n);
    cudaEventRecord(evNorms, 0);
    k_scanC<<<nscan, 1024>>>(n);

    // side stream: scale q by onorm once norms are ready (overlaps with place)
    cudaStreamWaitEvent(s1, evNorms, 0);
    k_scaleP<<<(n * 10 + 255) / 256, 256, 0, s1>>>(n);
    cudaEventRecord(evJoin, s1);

    k_place<<<(e + 255) / 256, 256>>>(src, dst, e);

    // join: gathers need both chains
    cudaStreamWaitEvent(0, evJoin, 0);
    k_gather1<<<(n * 10 + 255) / 256, 256>>>(n);
    k_gather2<<<(n * 10 + 255) / 256, 256>>>(b2, out, n);
}

// round 15
// speedup vs baseline: 1.2398x; 1.0409x over previous
#include <cuda_runtime.h>
#include <cuda_fp16.h>

// Problem constants (fixed by the dataset; runtime values cross-checked from in_sizes)
#define NN 100000
#define EE 1600000
#define RH 48   // fp16 row stride (48 halves = 96B = 3 sectors, 8B aligned chunks)

// ---------------- device scratch (static globals: no allocs allowed) ----------------
__device__ float  g_deg_out[NN];
__device__ float  g_deg_in[NN];
__device__ float  g_onorm[NN];
__device__ float  g_inorm[NN];
__device__ float  g_io[NN];            // onorm * inorm
__device__ float  g_q[NN * 40];        // x @ W12 (fp32, gemm output)
__device__ __half g_qh[NN * RH];       // onorm[row] * q[row]  (fp16 staged for gather1)
__device__ __half g_aggh[NN * RH];     // io[n] * gather(qh)   (fp16 staged for gather2)
__device__ float  g_son[NN];           // sum_{e:dst=n} onorm[src]
__device__ float  g_W12[256 * 40];     // W1 @ W2
__device__ float  g_c2[40];            // b1 @ W2
__device__ int    g_esrc[EE];          // CSR: src ids grouped by dst
__device__ int    g_rowpart[NN];       // per-block exclusive scan partials
__device__ int    g_rowstart[NN];      // CSR row offsets
__device__ int    g_cursor[NN];        // placement cursors
__device__ int    g_bsum[128];

// ---------------- small PTX helpers ----------------
__device__ __forceinline__ unsigned long long pack2(float lo, float hi) {
    unsigned long long r;
    asm("mov.b64 %0, {%1, %2};" : "=l"(r) : "f"(lo), "f"(hi));
    return r;
}
__device__ __forceinline__ void unpack2(unsigned long long v, float& lo, float& hi) {
    asm("mov.b64 {%0, %1}, %2;" : "=f"(lo), "=f"(hi) : "l"(v));
}
// packed dual-FMA: d.lo += a.lo*b.lo ; d.hi += a.hi*b.hi  (FFMA2 on sm_103a)
__device__ __forceinline__ void fma2(unsigned long long& d, unsigned long long a,
                                     unsigned long long b) {
    asm("fma.rn.f32x2 %0, %1, %2, %0;" : "+l"(d) : "l"(a), "l"(b));
}
// 4 halves (8B) -> float4
__device__ __forceinline__ float4 ld_h4(const __half* p) {
    uint2 r = *(const uint2*)p;
    __half2 a = *(__half2*)&r.x;
    __half2 b = *(__half2*)&r.y;
    float2 fa = __half22float2(a);
    float2 fb = __half22float2(b);
    return make_float4(fa.x, fa.y, fb.x, fb.y);
}
// float4 -> 4 halves (8B)
__device__ __forceinline__ void st_h4(__half* p, float4 v) {
    __half2 a = __floats2half2_rn(v.x, v.y);
    __half2 b = __floats2half2_rn(v.z, v.w);
    uint2 r;
    r.x = *(unsigned*)&a;
    r.y = *(unsigned*)&b;
    *(uint2*)p = r;
}

// Block-wide exclusive scan (all threads must participate). nwarps = blockDim/32.
__device__ __forceinline__ int block_exscan(int v, int* total, int nwarps) {
    __shared__ int wsum[32];
    int tid = threadIdx.x, lane = tid & 31, wid = tid >> 5;
    int inc = v;
#pragma unroll
    for (int o = 1; o < 32; o <<= 1) {
        int t = __shfl_up_sync(0xffffffffu, inc, o);
        if (lane >= o) inc += t;
    }
    if (lane == 31) wsum[wid] = inc;
    __syncthreads();
    if (wid == 0) {
        int s = (lane < nwarps) ? wsum[lane] : 0;
#pragma unroll
        for (int o = 1; o < 32; o <<= 1) {
            int t = __shfl_up_sync(0xffffffffu, s, o);
            if (lane >= o) s += t;
        }
        if (lane < nwarps) wsum[lane] = s;
    }
    __syncthreads();
    int base = (wid > 0) ? wsum[wid - 1] : 0;
    *total = wsum[nwarps - 1];
    return base + inc - v;
}

// ---------------- kernels ----------------

// Zero degree counters only (everything else is overwritten each replay)
__global__ void k_zero() {
    int i = blockIdx.x * blockDim.x + threadIdx.x;
    if (i < NN / 4) {
        float4 z = make_float4(0.f, 0.f, 0.f, 0.f);
        ((float4*)g_deg_out)[i] = z;
        ((float4*)g_deg_in)[i] = z;
    }
}

__global__ void k_degree(const int* __restrict__ src, const int* __restrict__ dst, int e_cnt) {
    int i = blockIdx.x * blockDim.x + threadIdx.x;
    if (i < e_cnt) {
        atomicAdd(&g_deg_out[src[i]], 1.0f);  // result unused -> REDG
        atomicAdd(&g_deg_in[dst[i]], 1.0f);
    }
}

// norms + scan phase A (per-block partial scan of in_deg)
__global__ __launch_bounds__(1024) void k_norms_scanA(int n) {
    int i = blockIdx.x * 1024 + threadIdx.x;
    float din = (i < n) ? g_deg_in[i] : 0.f;
    if (i < n) {
        float dout = g_deg_out[i];
        float on = rsqrtf(fmaxf(dout, 1.0f));
        float inr = rsqrtf(fmaxf(din, 1.0f));
        g_onorm[i] = on;
        g_inorm[i] = inr;
        g_io[i] = on * inr;
    }
    int total;
    int ex = block_exscan((int)din, &total, 32);
    if (i < n) g_rowpart[i] = ex;
    if (threadIdx.x == 0) g_bsum[blockIdx.x] = total;
}

// Scan phase B+C fused: each block reduces the block sums below it, then writes
// final row offsets + cursors for its 1024 nodes.
__global__ __launch_bounds__(1024) void k_scanC(int n) {
    __shared__ int red[32];
    __shared__ int s_off;
    int tid = threadIdx.x;
    int lane = tid & 31, wid = tid >> 5;
    int v = (tid < blockIdx.x) ? g_bsum[tid] : 0;  // blockIdx.x <= 97 < 1024
#pragma unroll
    for (int o = 16; o > 0; o >>= 1) v += __shfl_down_sync(0xffffffffu, v, o);
    if (lane == 0) red[wid] = v;
    __syncthreads();
    if (wid == 0) {
        int s = red[lane];
#pragma unroll
        for (int o = 16; o > 0; o >>= 1) s += __shfl_down_sync(0xffffffffu, s, o);
        if (lane == 0) s_off = s;
    }
    __syncthreads();
    int i = blockIdx.x * 1024 + tid;
    if (i < n) {
        int rs = g_rowpart[i] + s_off;
        g_rowstart[i] = rs;
        g_cursor[i] = rs;
    }
}

// CSR placement: group src ids by dst
__global__ void k_place(const int* __restrict__ src, const int* __restrict__ dst, int e_cnt) {
    int i = blockIdx.x * blockDim.x + threadIdx.x;
    if (i < e_cnt) {
        int pos = atomicAdd(&g_cursor[dst[i]], 1);
        g_esrc[pos] = src[i];
    }
}

// Precompute W12 = W1 @ W2 (256x40) and c2 = b1 @ W2 (40). W2 cached in smem.
// Runs on the side stream (no dependence on graph data).
__global__ __launch_bounds__(256) void k_prep(const float* __restrict__ W1,
                                              const float* __restrict__ W2,
                                              const float* __restrict__ b1) {
    __shared__ float Ws[64 * 40];
    int tid = threadIdx.x;
    for (int i = tid; i < 64 * 40; i += 256) Ws[i] = W2[i];
    __syncthreads();
    int gi = blockIdx.x * 256 + tid;
    if (gi < 256 * 40) {
        int r = gi / 40;
        int c = gi - r * 40;
        float s = 0.f;
#pragma unroll 16
        for (int k = 0; k < 64; k++) s = fmaf(W1[r * 64 + k], Ws[k * 40 + c], s);
        g_W12[gi] = s;
    }
    if (gi < 40) {
        float s = 0.f;
#pragma unroll 16
        for (int k = 0; k < 64; k++) s = fmaf(b1[k], Ws[k * 40 + gi], s);
        g_c2[gi] = s;
    }
}

// GEMM: q[n,40] = x[n,256] @ W12[256,40]   (no norm scaling -> input-only dep)
// Block tile 256 rows x 40 cols, BK=16, 256 threads, FFMA2 accumulators.
__global__ __launch_bounds__(256) void k_gemmQ(const float* __restrict__ x, int n) {
    __shared__ float As[16][258];  // [k][row], stride 258 -> conflict-free
    __shared__ float Bs[16][40];

    int tid = threadIdx.x;
    int brow = blockIdx.x * 256;
    int tx = tid & 7;    // cols tx*5 .. tx*5+4
    int ty = tid >> 3;   // rows ty*8 .. ty*8+7

    unsigned long long acc[4][5];
#pragma unroll
    for (int i = 0; i < 4; i++)
#pragma unroll
        for (int j = 0; j < 5; j++) acc[i][j] = 0ull;

    for (int k0 = 0; k0 < 256; k0 += 16) {
        // A tile: 256 rows x 16 k, transposed (4 float4 loads/thread)
#pragma unroll
        for (int t = 0; t < 4; t++) {
            int idx = tid + t * 256;     // 0..1023
            int row = idx >> 2;          // 0..255
            int kk = (idx & 3) << 2;     // 0,4,8,12
            int gr = brow + row;
            float4 v = make_float4(0.f, 0.f, 0.f, 0.f);
            if (gr < n) v = *(const float4*)(x + (size_t)gr * 256 + k0 + kk);
            As[kk + 0][row] = v.x;
            As[kk + 1][row] = v.y;
            As[kk + 2][row] = v.z;
            As[kk + 3][row] = v.w;
        }
        // B tile 16x40 (scalar)
#pragma unroll
        for (int t = 0; t < 3; t++) {
            int idx = tid + t * 256;
            if (idx < 640) {
                int kr = idx / 40;
                int c = idx - kr * 40;
                Bs[kr][c] = g_W12[(k0 + kr) * 40 + c];
            }
        }
        __syncthreads();

#pragma unroll
        for (int k = 0; k < 16; k++) {
            unsigned long long b[5];
#pragma unroll
            for (int j = 0; j < 5; j++) {
                float w = Bs[k][tx * 5 + j];
                b[j] = pack2(w, w);
            }
#pragma unroll
            for (int i2 = 0; i2 < 4; i2++) {
                unsigned long long ap =
                    *(const unsigned long long*)&As[k][(ty << 3) + (i2 << 1)];
#pragma unroll
                for (int j = 0; j < 5; j++) fma2(acc[i2][j], ap, b[j]);
            }
        }
        __syncthreads();
    }

    // store q
#pragma unroll
    for (int i2 = 0; i2 < 4; i2++) {
        int r0 = brow + (ty << 3) + (i2 << 1);
        float lo[5], hi[5];
#pragma unroll
        for (int j = 0; j < 5; j++) unpack2(acc[i2][j], lo[j], hi[j]);
        if (r0 < n) {
#pragma unroll
            for (int j = 0; j < 5; j++) g_q[(size_t)r0 * 40 + tx * 5 + j] = lo[j];
        }
        if (r0 + 1 < n) {
#pragma unroll
            for (int j = 0; j < 5; j++) g_q[(size_t)(r0 + 1) * 40 + tx * 5 + j] = hi[j];
        }
    }
}

// Scale + fp16 convert: qh[row, c..c+3] = half(onorm[row] * q[row, c..c+3])
// (side stream after evNorms, overlapped with k_place on the main stream)
__global__ void k_scaleP(int n) {
    int i = blockIdx.x * blockDim.x + threadIdx.x;  // float4-chunk index
    if (i >= n * 10) return;
    int row = i / 10;
    int c = (i - row * 10) << 2;
    float o = g_onorm[row];
    float4 v = *(const float4*)(g_q + (size_t)row * 40 + c);
    st_h4(g_qh + (size_t)row * RH + c,
          make_float4(v.x * o, v.y * o, v.z * o, v.w * o));
}

// Gather 1 (thread = (node, 4-elem chunk)):
// aggh[node] = half( io[node] * sum_{e: dst=node} qh[src_e] )
// chunk-0 lane additionally accumulates son[node] = sum onorm[src_e]
__global__ void k_gather1(int n) {
    int i = blockIdx.x * blockDim.x + threadIdx.x;
    if (i >= n * 10) return;
    int node = i / 10;
    int ch = i - node * 10;
    int c = ch << 2;
    int start = g_rowstart[node];
    int deg = (int)g_deg_in[node];
    const int* ep = g_esrc + start;
    bool lead = (ch == 0);
    float4 acc = make_float4(0.f, 0.f, 0.f, 0.f);
    float son = 0.f;
    int j = 0;
    for (; j + 4 <= deg; j += 4) {
        int s0 = ep[j], s1 = ep[j + 1], s2 = ep[j + 2], s3 = ep[j + 3];
        float4 v0 = ld_h4(g_qh + (size_t)s0 * RH + c);
        float4 v1 = ld_h4(g_qh + (size_t)s1 * RH + c);
        float4 v2 = ld_h4(g_qh + (size_t)s2 * RH + c);
        float4 v3 = ld_h4(g_qh + (size_t)s3 * RH + c);
        if (lead) { son += g_onorm[s0] + g_onorm[s1] + g_onorm[s2] + g_onorm[s3]; }
        acc.x += v0.x; acc.y += v0.y; acc.z += v0.z; acc.w += v0.w;
        acc.x += v1.x; acc.y += v1.y; acc.z += v1.z; acc.w += v1.w;
        acc.x += v2.x; acc.y += v2.y; acc.z += v2.z; acc.w += v2.w;
        acc.x += v3.x; acc.y += v3.y; acc.z += v3.z; acc.w += v3.w;
    }
    for (; j < deg; j++) {
        int s = ep[j];
        float4 v = ld_h4(g_qh + (size_t)s * RH + c);
        if (lead) son += g_onorm[s];
        acc.x += v.x; acc.y += v.y; acc.z += v.z; acc.w += v.w;
    }
    float io = g_io[node];
    st_h4(g_aggh + (size_t)node * RH + c,
          make_float4(acc.x * io, acc.y * io, acc.z * io, acc.w * io));
    if (lead) g_son[node] = son;
}

// Gather 2 + epilogue:
// out[d] = inorm[d] * ( sum aggh[src] + c2 * son[d] ) + b2
__global__ void k_gather2(const float* __restrict__ b2, float* __restrict__ out, int n) {
    int i = blockIdx.x * blockDim.x + threadIdx.x;
    if (i >= n * 10) return;
    int node = i / 10;
    int c = (i - node * 10) << 2;
    int start = g_rowstart[node];
    int deg = (int)g_deg_in[node];
    const int* ep = g_esrc + start;
    float4 acc = make_float4(0.f, 0.f, 0.f, 0.f);
    int j = 0;
    for (; j + 4 <= deg; j += 4) {
        int s0 = ep[j], s1 = ep[j + 1], s2 = ep[j + 2], s3 = ep[j + 3];
        float4 v0 = ld_h4(g_aggh + (size_t)s0 * RH + c);
        float4 v1 = ld_h4(g_aggh + (size_t)s1 * RH + c);
        float4 v2 = ld_h4(g_aggh + (size_t)s2 * RH + c);
        float4 v3 = ld_h4(g_aggh + (size_t)s3 * RH + c);
        acc.x += v0.x; acc.y += v0.y; acc.z += v0.z; acc.w += v0.w;
        acc.x += v1.x; acc.y += v1.y; acc.z += v1.z; acc.w += v1.w;
        acc.x += v2.x; acc.y += v2.y; acc.z += v2.z; acc.w += v2.w;
        acc.x += v3.x; acc.y += v3.y; acc.z += v3.z; acc.w += v3.w;
    }
    for (; j < deg; j++) {
        int s = ep[j];
        float4 v = ld_h4(g_aggh + (size_t)s * RH + c);
        acc.x += v.x; acc.y += v.y; acc.z += v.z; acc.w += v.w;
    }
    float son = g_son[node];
    float4 c2 = *(const float4*)(g_c2 + c);
    float4 bb = *(const float4*)(b2 + c);
    float inr = g_inorm[node];
    *(float4*)(out + (size_t)node * 40 + c) =
        make_float4(fmaf(inr, fmaf(c2.x, son, acc.x), bb.x),
                    fmaf(inr, fmaf(c2.y, son, acc.y), bb.y),
                    fmaf(inr, fmaf(c2.z, son, acc.z), bb.z),
                    fmaf(inr, fmaf(c2.w, son, acc.w), bb.w));
}

// ---------------- launch ----------------
// DAG (graph capture encodes the fork/join):
//   main:  zero -> degree -> norms/scanA -> scanC -> place -> [join] -> gather1 -> gather2
//   side:  prep -> gemmQ -> [wait norms] -> scaleP(+fp16) -> [join]
extern "C" void kernel_launch(void* const* d_in, const int* in_sizes, int n_in,
                              void* d_out, int out_size) {
    const float* x  = (const float*)d_in[0];
    const int* src  = (const int*)d_in[1];
    const int* dst  = (const int*)d_in[2];
    const float* W1 = (const float*)d_in[3];
    const float* b1 = (const float*)d_in[4];
    const float* W2 = (const float*)d_in[5];
    const float* b2 = (const float*)d_in[6];
    float* out = (float*)d_out;

    int n = in_sizes[0] / 256;   // 100000
    int e = in_sizes[1];         // 1600000

    int nscan = (n + 1023) / 1024;  // 98

    static bool s_init = false;
    static cudaStream_t s1;
    static cudaEvent_t evFork, evNorms, evJoin;
    if (!s_init) {  // one-time infra setup (first call is outside graph capture)
        cudaStreamCreateWithFlags(&s1, cudaStreamNonBlocking);
        cudaEventCreateWithFlags(&evFork, cudaEventDisableTiming);
        cudaEventCreateWithFlags(&evNorms, cudaEventDisableTiming);
        cudaEventCreateWithFlags(&evJoin, cudaEventDisableTiming);
        s_init = true;
    }

    // fork side stream off the (captured) default stream
    cudaEventRecord(evFork, 0);
    cudaStreamWaitEvent(s1, evFork, 0);
    k_prep<<<40, 256, 0, s1>>>(W1, W2, b1);
    k_gemmQ<<<(n + 255) / 256, 256, 0, s1>>>(x, n);

    // main chain on the default stream
    k_zero<<<(NN / 4 + 255) / 256, 256>>>();
    k_degree<<<(e + 255) / 256, 256>>>(src, dst, e);
    k_norms_scanA<<<nscan, 1024>>>(n);
    cudaEventRecord(evNorms, 0);
    k_scanC<<<nscan, 1024>>>(n);

    // side stream: scale+convert q once norms are ready (overlaps with place)
    cudaStreamWaitEvent(s1, evNorms, 0);
    k_scaleP<<<(n * 10 + 255) / 256, 256, 0, s1>>>(n);
    cudaEventRecord(evJoin, s1);

    k_place<<<(e + 255) / 256, 256>>>(src, dst, e);

    // join: gathers need both chains
    cudaStreamWaitEvent(0, evJoin, 0);
    k_gather1<<<(n * 10 + 255) / 256, 256>>>(n);
    k_gather2<<<(n * 10 + 255) / 256, 256>>>(b2, out, n);
}